// round 1
// baseline (speedup 1.0000x reference)
#include <cuda_runtime.h>
#include <math.h>

#define Bn 8
#define C 128
#define HW 16384
#define Ncls 16
#define EPSF 1e-7f

// ---------------- scratch (no allocations allowed) ----------------
__device__ float g_G[Bn*C*C];      // per-batch Gram x x^T
__device__ float g_sx[Bn*C];       // per-batch channel sums
__device__ float g_H[Bn*3*C*C];    // H_m = G @ W_m^T  for m in {Wr, Wsa, Wo}
__device__ float g_M[Bn*C*C];      // fused output matrix (sigma*A*Wo + I)
__device__ float g_d[Bn*C];        // fused output bias

// ---------------- zero scratch ----------------
__global__ void zero_kernel() {
    int i = blockIdx.x * blockDim.x + threadIdx.x;
    if (i < Bn*C*C) g_G[i] = 0.f;
    if (i < Bn*C)   g_sx[i] = 0.f;
}

// ---------------- Gram: G[b] = x[b] @ x[b]^T, sx[b] = rowsum ----------------
// grid (32, 8): 32 pixel-chunks of 512 per batch. block 256 threads, 8x8 per thread.
__global__ __launch_bounds__(256) void gram_kernel(const float* __restrict__ x) {
    const int b  = blockIdx.y;
    const int p0 = blockIdx.x * 512;
    const float* xb = x + b * (C * HW);
    __shared__ float xs[C][33];
    const int tid = threadIdx.x;
    const int tx = tid & 15, ty = tid >> 4;
    const int kk = tid & 31, c0 = tid >> 5;

    float accA[4][4] = {}, accB[4][4] = {}, accC[4][4] = {}, accD[4][4] = {};
    float ssum = 0.f;

    for (int kt = 0; kt < 512; kt += 32) {
        #pragma unroll
        for (int i = 0; i < 16; i++) {
            int c = c0 + i * 8;
            xs[c][kk] = xb[c * HW + p0 + kt + kk];
        }
        __syncthreads();
        #pragma unroll 4
        for (int k = 0; k < 32; k++) {
            float a0[4], a1[4], b0[4], b1[4];
            #pragma unroll
            for (int i = 0; i < 4; i++) { a0[i] = xs[ty*4+i][k];    a1[i] = xs[64+ty*4+i][k]; }
            #pragma unroll
            for (int j = 0; j < 4; j++) { b0[j] = xs[tx*4+j][k];    b1[j] = xs[64+tx*4+j][k]; }
            #pragma unroll
            for (int i = 0; i < 4; i++)
                #pragma unroll
                for (int j = 0; j < 4; j++) {
                    accA[i][j] = fmaf(a0[i], b0[j], accA[i][j]);
                    accB[i][j] = fmaf(a0[i], b1[j], accB[i][j]);
                    accC[i][j] = fmaf(a1[i], b0[j], accC[i][j]);
                    accD[i][j] = fmaf(a1[i], b1[j], accD[i][j]);
                }
        }
        if (tid < C) {
            #pragma unroll 8
            for (int k = 0; k < 32; k++) ssum += xs[tid][k];
        }
        __syncthreads();
    }

    float* Gb = g_G + b * C * C;
    #pragma unroll
    for (int i = 0; i < 4; i++) {
        int r0 = ty*4 + i, r1 = 64 + ty*4 + i;
        #pragma unroll
        for (int j = 0; j < 4; j++) {
            int q0 = tx*4 + j, q1 = 64 + tx*4 + j;
            atomicAdd(&Gb[r0*C + q0], accA[i][j]);
            atomicAdd(&Gb[r0*C + q1], accB[i][j]);
            atomicAdd(&Gb[r1*C + q0], accC[i][j]);
            atomicAdd(&Gb[r1*C + q1], accD[i][j]);
        }
    }
    if (tid < C) atomicAdd(&g_sx[b*C + tid], ssum);
}

// ---------------- H_m[b] = G[b] @ W_m^T   (H[i][c] = sum_j G[i][j] W[c][j]) ----------------
// grid (3, 8)
__global__ __launch_bounds__(256) void hgemm_kernel(const float* __restrict__ Wr,
                                                    const float* __restrict__ Wsa,
                                                    const float* __restrict__ Wo) {
    const int m = blockIdx.x;
    const int b = blockIdx.y;
    const float* W = (m == 0) ? Wr : (m == 1) ? Wsa : Wo;
    const float* G = g_G + b * C * C;
    float* H = g_H + (b * 3 + m) * C * C;

    __shared__ float As[C][33];
    __shared__ float Bs[C][33];
    const int tid = threadIdx.x;
    const int tx = tid & 15, ty = tid >> 4;
    const int kk = tid & 31, r0w = tid >> 5;

    float accA[4][4] = {}, accB[4][4] = {}, accC[4][4] = {}, accD[4][4] = {};

    for (int k0 = 0; k0 < C; k0 += 32) {
        #pragma unroll
        for (int i = 0; i < 16; i++) {
            int r = r0w + i * 8;
            As[r][kk] = G[r*C + k0 + kk];
            Bs[r][kk] = W[r*C + k0 + kk];
        }
        __syncthreads();
        #pragma unroll 4
        for (int k = 0; k < 32; k++) {
            float a0[4], a1[4], b0[4], b1[4];
            #pragma unroll
            for (int i = 0; i < 4; i++) { a0[i] = As[ty*4+i][k]; a1[i] = As[64+ty*4+i][k]; }
            #pragma unroll
            for (int j = 0; j < 4; j++) { b0[j] = Bs[tx*4+j][k]; b1[j] = Bs[64+tx*4+j][k]; }
            #pragma unroll
            for (int i = 0; i < 4; i++)
                #pragma unroll
                for (int j = 0; j < 4; j++) {
                    accA[i][j] = fmaf(a0[i], b0[j], accA[i][j]);
                    accB[i][j] = fmaf(a0[i], b1[j], accB[i][j]);
                    accC[i][j] = fmaf(a1[i], b0[j], accC[i][j]);
                    accD[i][j] = fmaf(a1[i], b1[j], accD[i][j]);
                }
        }
        __syncthreads();
    }

    #pragma unroll
    for (int i = 0; i < 4; i++) {
        int r0 = ty*4 + i, r1 = 64 + ty*4 + i;
        #pragma unroll
        for (int j = 0; j < 4; j++) {
            int q0 = tx*4 + j, q1 = 64 + tx*4 + j;
            H[r0*C + q0] = accA[i][j];
            H[r0*C + q1] = accB[i][j];
            H[r1*C + q0] = accC[i][j];
            H[r1*C + q1] = accD[i][j];
        }
    }
}

// ---------------- mid: all small math -> M[b], d[b] ----------------
// grid 8, block 128
__global__ __launch_bounds__(128) void mid_kernel(
    const float* __restrict__ Wsa, const float* __restrict__ bsa,
    const float* __restrict__ Wr,  const float* __restrict__ br,
    const float* __restrict__ kn,
    const float* __restrict__ Wo,  const float* __restrict__ bo,
    const float* __restrict__ alpha, const float* __restrict__ sigma)
{
    const int b = blockIdx.x;
    const int tid = threadIdx.x;          // 0..127, c = tid
    const int c = tid;
    const float* G  = g_G + b*C*C;
    const float* Hr = g_H + (b*3 + 0)*C*C;
    const float* Hs = g_H + (b*3 + 1)*C*C;
    const float* Ho = g_H + (b*3 + 2)*C*C;

    __shared__ float s_sh[C], u_sh[C], m_sh[C], s1_sh[C], s2_sh[C], A_sh[C];
    __shared__ float att_sh[Ncls][C];
    __shared__ float Q_sh[Ncls][C];
    __shared__ float nxn_sh[Ncls], inv_sh[Ncls], minv_sh[Ncls], kns_sh[Ncls];
    __shared__ float red_mx, red_sum;

    const float hwf = 16384.f;

    // channel sums + colsum of Wsa
    s_sh[tid] = g_sx[b*C + tid];
    {
        float u = 0.f;
        for (int i = 0; i < C; i++) u += Wsa[i*C + tid];
        u_sh[tid] = u;
    }
    __syncthreads();

    // kn . s  (threads 0..15)
    if (tid < Ncls) {
        float t = 0.f;
        for (int k = 0; k < C; k++) t = fmaf(kn[tid*C + k], s_sh[k], t);
        kns_sh[tid] = t;
    }

    // Q = kn @ G (for norm_xn)
    {
        float q[Ncls];
        #pragma unroll
        for (int n = 0; n < Ncls; n++) q[n] = 0.f;
        for (int k = 0; k < C; k++) {
            float g = G[k*C + c];
            #pragma unroll
            for (int n = 0; n < Ncls; n++) q[n] = fmaf(kn[n*C + k], g, q[n]);
        }
        #pragma unroll
        for (int n = 0; n < Ncls; n++) Q_sh[n][c] = q[n];
    }
    __syncthreads();
    if (tid < Ncls) {
        float t = 0.f;
        for (int i = 0; i < C; i++) t = fmaf(Q_sh[tid][i], kn[tid*C + i], t);
        nxn_sh[tid] = sqrtf(t);
    }
    __syncthreads();

    // ---- per-channel heavy pass ----
    float rel[Ncls];
    #pragma unroll
    for (int n = 0; n < Ncls; n++) rel[n] = 0.f;
    float nxr2 = 0.f, dsa = 0.f, s2v = 0.f, csum = 0.f;
    float wr_s = 0.f, wsa_s = 0.f, wo_s = 0.f;

    for (int i = 0; i < C; i++) {
        float hr = Hr[i*C + c];
        float hs = Hs[i*C + c];
        float ho = Ho[i*C + c];
        float wri = Wr[c*C + i], wsi = Wsa[c*C + i], woi = Wo[c*C + i];
        float si  = s_sh[i];
        nxr2 = fmaf(wri, hr, nxr2);
        dsa  = fmaf(wsi, hs, dsa);
        s2v  = fmaf(woi, ho, s2v);
        csum = fmaf(u_sh[i], hs, csum);
        wr_s = fmaf(wri, si, wr_s);
        wsa_s= fmaf(wsi, si, wsa_s);
        wo_s = fmaf(woi, si, wo_s);
        #pragma unroll
        for (int n = 0; n < Ncls; n++) rel[n] = fmaf(kn[n*C + i], hr, rel[n]);
    }
    float sb = 0.f, us = 0.f;
    for (int i = 0; i < C; i++) { sb += bsa[i]; us = fmaf(u_sh[i], s_sh[i], us); }

    float brc = br[c], bsc = bsa[c], boc = bo[c];
    nxr2 += 2.f*brc*wr_s + hwf*brc*brc;
    float nxr = sqrtf(nxr2);
    dsa  += 2.f*bsc*wsa_s + hwf*bsc*bsc;
    csum += sb*wsa_s + bsc*us + hwf*sb*bsc;
    m_sh[c]  = (csum - dsa) * (1.f/128.f);
    s1_sh[c] = wo_s + hwf*boc;
    s2_sh[c] = s2v + 2.f*boc*wo_s + hwf*boc*boc;
    __syncthreads();

    // regular = softmax over c of m
    if (tid == 0) {
        float mx = -1e30f;
        for (int j = 0; j < C; j++) mx = fmaxf(mx, m_sh[j]);
        float s = 0.f;
        for (int j = 0; j < C; j++) s += expf(m_sh[j] - mx);
        red_mx = mx; red_sum = s;
    }
    __syncthreads();
    float regular = expf(m_sh[c] - red_mx) / red_sum;

    // relation_norm + alpha*regular, softmax over n -> att
    {
        float rn[Ncls];
        float mxn = -1e30f;
        #pragma unroll
        for (int n = 0; n < Ncls; n++) {
            float r = rel[n] + brc * kns_sh[n];
            float al = fminf(fmaxf(alpha[n], 0.f), 1.f);
            rn[n] = r / (nxn_sh[n]*nxr + EPSF) + al * regular;
            mxn = fmaxf(mxn, rn[n]);
        }
        float se = 0.f;
        #pragma unroll
        for (int n = 0; n < Ncls; n++) { rn[n] = expf(rn[n] - mxn); se += rn[n]; }
        float ise = 1.f / se;
        #pragma unroll
        for (int n = 0; n < Ncls; n++) att_sh[n][c] = rn[n] * ise;
    }
    __syncthreads();

    // per-class group-norm stats
    if (tid < Ncls) {
        int n = tid;
        float cnt = 0.f, hot = 0.f, sq2 = 0.f;
        for (int cc = 0; cc < C; cc++) {
            float a = att_sh[n][cc];
            cnt += a;
            hot = fmaf(a, s1_sh[cc], hot);
            sq2 = fmaf(a*a, s2_sh[cc], sq2);
        }
        cnt = cnt * hwf + EPSF;
        float mean = hot / cnt;
        float sq = sq2 - 2.f*mean*hot + mean*mean*(128.f*hwf);
        float stdv = sqrtf(sq / cnt);
        float inv = 1.f / (stdv + EPSF);
        inv_sh[n] = inv; minv_sh[n] = mean * inv;
    }
    __syncthreads();

    // A, B, d
    {
        float Av = 0.f, Bv = 0.f;
        #pragma unroll
        for (int n = 0; n < Ncls; n++) {
            float a = att_sh[n][c];
            Av = fmaf(a, inv_sh[n],  Av);
            Bv = fmaf(a, minv_sh[n], Bv);
        }
        A_sh[c] = Av;
        float sg = sigma[0];
        g_d[b*C + c] = sg * (Av * bo[c] - Bv);
    }
    __syncthreads();

    // M = sigma*diag(A)*Wo + I
    {
        float sg = sigma[0];
        for (int t = tid; t < C*C; t += 128) {
            int o = t >> 7, cc = t & 127;
            float v = sg * A_sh[o] * Wo[t];
            if (o == cc) v += 1.f;
            g_M[b*C*C + t] = v;
        }
    }
}

// ---------------- orthogonality loss ----------------
__global__ void loss_kernel(const float* __restrict__ kn, float* __restrict__ out, int out_size) {
    __shared__ float sym[Ncls][Ncls];
    __shared__ float partial[256];
    int tid = threadIdx.x;
    int i = tid >> 4, j = tid & 15;
    float dot = 0.f;
    for (int k = 0; k < C; k++) dot = fmaf(kn[i*C + k], kn[j*C + k], dot);
    sym[i][j] = dot;
    __syncthreads();
    float nr = sqrtf(sym[i][i]) * sqrtf(sym[j][j]);
    float l = sym[i][j] / (nr + EPSF) - (i == j ? 1.f : 0.f);
    partial[tid] = l * l;
    __syncthreads();
    for (int s = 128; s > 0; s >>= 1) {
        if (tid < s) partial[tid] += partial[tid + s];
        __syncthreads();
    }
    if (tid == 0) {
        float loss = 0.1f * logf(partial[0] + 1.f);
        for (int idx = Bn*C*HW; idx < out_size; idx++) out[idx] = loss;
    }
}

// ---------------- out = M[b] @ x[b] + d[b] ----------------
// grid (128 pixel-tiles, 8 batches)
__global__ __launch_bounds__(256) void out_kernel(const float* __restrict__ x,
                                                  float* __restrict__ out) {
    const int b  = blockIdx.y;
    const int p0 = blockIdx.x * 128;
    const float* Mb = g_M + b*C*C;
    const float* xb = x + b * (C * HW);
    float* ob = out + b * (C * HW);

    __shared__ float Ms[C][33];
    __shared__ float xsh[32][132];
    const int tid = threadIdx.x;
    const int tx = tid & 15, ty = tid >> 4;

    float accA[4][4] = {}, accB[4][4] = {}, accC[4][4] = {}, accD[4][4] = {};

    for (int k0 = 0; k0 < C; k0 += 32) {
        {
            int kk = tid & 31, o0 = tid >> 5;
            #pragma unroll
            for (int i = 0; i < 16; i++) {
                int o = o0 + i * 8;
                Ms[o][kk] = Mb[o*C + k0 + kk];
            }
        }
        {
            #pragma unroll
            for (int t = 0; t < 4; t++) {
                int idx = tid + t * 256;
                int kk = idx >> 5, pp = (idx & 31) * 4;
                float4 v = *reinterpret_cast<const float4*>(&xb[(k0 + kk)*HW + p0 + pp]);
                *reinterpret_cast<float4*>(&xsh[kk][pp]) = v;
            }
        }
        __syncthreads();
        #pragma unroll 4
        for (int k = 0; k < 32; k++) {
            float a0[4], a1[4];
            #pragma unroll
            for (int i = 0; i < 4; i++) { a0[i] = Ms[ty*4+i][k]; a1[i] = Ms[64+ty*4+i][k]; }
            float4 bv0 = *reinterpret_cast<const float4*>(&xsh[k][tx*4]);
            float4 bv1 = *reinterpret_cast<const float4*>(&xsh[k][64 + tx*4]);
            float b0[4] = {bv0.x, bv0.y, bv0.z, bv0.w};
            float b1[4] = {bv1.x, bv1.y, bv1.z, bv1.w};
            #pragma unroll
            for (int i = 0; i < 4; i++)
                #pragma unroll
                for (int j = 0; j < 4; j++) {
                    accA[i][j] = fmaf(a0[i], b0[j], accA[i][j]);
                    accB[i][j] = fmaf(a0[i], b1[j], accB[i][j]);
                    accC[i][j] = fmaf(a1[i], b0[j], accC[i][j]);
                    accD[i][j] = fmaf(a1[i], b1[j], accD[i][j]);
                }
        }
        __syncthreads();
    }

    #pragma unroll
    for (int i = 0; i < 4; i++) {
        int o0 = ty*4 + i, o1 = 64 + ty*4 + i;
        float d0 = g_d[b*C + o0], d1 = g_d[b*C + o1];
        float4 v;
        v.x = accA[i][0] + d0; v.y = accA[i][1] + d0; v.z = accA[i][2] + d0; v.w = accA[i][3] + d0;
        *reinterpret_cast<float4*>(&ob[o0*HW + p0 + tx*4]) = v;
        v.x = accB[i][0] + d0; v.y = accB[i][1] + d0; v.z = accB[i][2] + d0; v.w = accB[i][3] + d0;
        *reinterpret_cast<float4*>(&ob[o0*HW + p0 + 64 + tx*4]) = v;
        v.x = accC[i][0] + d1; v.y = accC[i][1] + d1; v.z = accC[i][2] + d1; v.w = accC[i][3] + d1;
        *reinterpret_cast<float4*>(&ob[o1*HW + p0 + tx*4]) = v;
        v.x = accD[i][0] + d1; v.y = accD[i][1] + d1; v.z = accD[i][2] + d1; v.w = accD[i][3] + d1;
        *reinterpret_cast<float4*>(&ob[o1*HW + p0 + 64 + tx*4]) = v;
    }
}

extern "C" void kernel_launch(void* const* d_in, const int* in_sizes, int n_in,
                              void* d_out, int out_size) {
    const float* x     = (const float*)d_in[0];
    const float* Wsa   = (const float*)d_in[1];
    const float* bsa   = (const float*)d_in[2];
    const float* Wr    = (const float*)d_in[3];
    const float* br    = (const float*)d_in[4];
    const float* kn    = (const float*)d_in[5];
    const float* Wo    = (const float*)d_in[6];
    const float* bo    = (const float*)d_in[7];
    const float* alpha = (const float*)d_in[8];
    const float* sigma = (const float*)d_in[9];
    float* out = (float*)d_out;

    zero_kernel<<<(Bn*C*C + 255) / 256, 256>>>();
    gram_kernel<<<dim3(32, Bn), 256>>>(x);
    hgemm_kernel<<<dim3(3, Bn), 256>>>(Wr, Wsa, Wo);
    mid_kernel<<<Bn, 128>>>(Wsa, bsa, Wr, br, kn, Wo, bo, alpha, sigma);
    loss_kernel<<<1, 256>>>(kn, out, out_size);
    out_kernel<<<dim3(128, Bn), 256>>>(x, out);
}